// round 3
// baseline (speedup 1.0000x reference)
#include <cuda_runtime.h>
#include <math.h>
#include <stdint.h>

#define BB    64
#define HH    56
#define WWD   56
#define CC    256
#define NHEAD 8
#define WS    7
#define SS    3
#define NN    49            // WS*WS
#define HID   1024
#define NWIN  64            // (HH/WS)*(WWD/WS)
#define BWIN  (BB*NWIN)     // 4096 windows total
#define MTOK  (BB*HH*WWD)   // 200704 tokens
#define HD    32            // CC/NHEAD

// Scratch (static device globals; no allocations allowed).
// g_bufA = 4 "quarters" of MTOK*CC floats each: q,k,v during attention,
//          then reused whole as the MLP hidden [MTOK, HID] (HID == 4*CC).
// g_bufB = 2 halves of MTOK*CC: {hw -> x1} and {attnout -> h2}.
__device__ float g_bufA[205520896];   // MTOK*HID
__device__ float g_bufB[102760448];   // MTOK*2*CC

// ---------------------------------------------------------------------------
// LayerNorm kernel. windowed=1: also applies cyclic shift (-SS,-SS) and window
// partition so output row order is [win (b-major), n] matching attention.
// ---------------------------------------------------------------------------
__global__ void __launch_bounds__(256)
ln_kernel(const float* __restrict__ x, const float* __restrict__ wt,
          const float* __restrict__ bs, float* __restrict__ out, int windowed)
{
    int m = blockIdx.x;
    int c = threadIdx.x;
    size_t src;
    if (windowed) {
        int win = m / NN, n = m - win * NN;
        int b = win >> 6, w = win & 63;
        int wr = w >> 3, wc = w & 7;
        int ir = n / 7, ic = n - ir * 7;
        int hs = wr * WS + ir + SS; if (hs >= HH)  hs -= HH;   // shifted[h]=orig[(h+3)%56]
        int wsd = wc * WS + ic + SS; if (wsd >= WWD) wsd -= WWD;
        src = (size_t)b * (HH * WWD) + hs * WWD + wsd;
    } else {
        src = (size_t)m;
    }
    float v = x[src * CC + c];
    float s = v, sq = v * v;
#pragma unroll
    for (int off = 16; off; off >>= 1) {
        s  += __shfl_xor_sync(0xffffffffu, s,  off);
        sq += __shfl_xor_sync(0xffffffffu, sq, off);
    }
    __shared__ float ss[8], ssq[8];
    int wid = c >> 5, lid = c & 31;
    if (lid == 0) { ss[wid] = s; ssq[wid] = sq; }
    __syncthreads();
    float ts = 0.f, tsq = 0.f;
#pragma unroll
    for (int i = 0; i < 8; i++) { ts += ss[i]; tsq += ssq[i]; }
    float mean = ts * (1.f / CC);
    float var  = tsq * (1.f / CC) - mean * mean;
    float r = rsqrtf(var + 1e-5f);
    out[(size_t)m * CC + c] = (v - mean) * r * wt[c] + bs[c];
}

// ---------------------------------------------------------------------------
// Generic SGEMM: Cmn = A[M,K] @ W[N,K]^T, 128x128 tile, 8x8 microtile, BK=8,
// single-stage smem with register prefetch. Fused epilogues:
//  EPI 0: qkv  -> scatter to q/k/v [win, head, n, hd], q scaled by hd^-0.5
//  EPI 1: proj -> window-reverse + unshift + residual add with aux (=x)
//  EPI 2: fc1  -> exact GELU
//  EPI 3: fc2  -> residual add with aux (=x1)
// All dims (M=200704, N in {256,768,1024}, K in {256,1024}) divide tiles exactly.
// ---------------------------------------------------------------------------
template<int EPI>
__global__ void __launch_bounds__(256)
gemm_kernel(const float* __restrict__ A, const float* __restrict__ W,
            const float* __restrict__ bias, const float* __restrict__ aux,
            float* __restrict__ out0, float* __restrict__ out1,
            float* __restrict__ out2, int K, int Nn)
{
    const int BM = 128, BN = 128, BK = 8;
    __shared__ float As[BK][BM + 4];
    __shared__ float Bs[BK][BN + 4];
    const int bm = blockIdx.y * BM;
    const int bn = blockIdx.x * BN;
    const int tid = threadIdx.x;
    const int tx = tid & 15, ty = tid >> 4;
    const int lr = tid >> 1;
    const int lc = (tid & 1) * 4;

    const float* Aptr = A + (size_t)(bm + lr) * K + lc;
    const float* Wptr = W + (size_t)(bn + lr) * K + lc;

    float acc[8][8];
#pragma unroll
    for (int i = 0; i < 8; i++)
#pragma unroll
        for (int j = 0; j < 8; j++) acc[i][j] = 0.f;

    float4 av = *(const float4*)Aptr;
    float4 bv = *(const float4*)Wptr;

    for (int k0 = 0; k0 < K; k0 += BK) {
        As[lc + 0][lr] = av.x; As[lc + 1][lr] = av.y;
        As[lc + 2][lr] = av.z; As[lc + 3][lr] = av.w;
        Bs[lc + 0][lr] = bv.x; Bs[lc + 1][lr] = bv.y;
        Bs[lc + 2][lr] = bv.z; Bs[lc + 3][lr] = bv.w;
        __syncthreads();
        if (k0 + BK < K) {
            av = *(const float4*)(Aptr + k0 + BK);
            bv = *(const float4*)(Wptr + k0 + BK);
        }
#pragma unroll
        for (int kk = 0; kk < BK; kk++) {
            float ra[8], rb[8];
            *(float4*)&ra[0] = *(const float4*)&As[kk][ty * 8];
            *(float4*)&ra[4] = *(const float4*)&As[kk][ty * 8 + 4];
            *(float4*)&rb[0] = *(const float4*)&Bs[kk][tx * 8];
            *(float4*)&rb[4] = *(const float4*)&Bs[kk][tx * 8 + 4];
#pragma unroll
            for (int i = 0; i < 8; i++)
#pragma unroll
                for (int j = 0; j < 8; j++)
                    acc[i][j] = fmaf(ra[i], rb[j], acc[i][j]);
        }
        __syncthreads();
    }

    const int o0 = bn + tx * 8;
#pragma unroll
    for (int i = 0; i < 8; i++) {
        int m = bm + ty * 8 + i;
        if (EPI == 0) {
            int win = m / NN, n = m - win * NN;
            int s = o0 >> 8;
            int h = (o0 >> 5) & 7;
            int d0 = o0 & 31;                      // 8 consecutive d, same s/h
            float sc = (s == 0) ? 0.17677669529663687f : 1.0f;
            float* dst = (s == 0) ? out0 : (s == 1) ? out1 : out2;
            size_t off = (size_t)(win * (NHEAD * NN) + h * NN + n) * HD + d0;
            float4 v0, v1;
            v0.x = (acc[i][0] + bias[o0 + 0]) * sc;
            v0.y = (acc[i][1] + bias[o0 + 1]) * sc;
            v0.z = (acc[i][2] + bias[o0 + 2]) * sc;
            v0.w = (acc[i][3] + bias[o0 + 3]) * sc;
            v1.x = (acc[i][4] + bias[o0 + 4]) * sc;
            v1.y = (acc[i][5] + bias[o0 + 5]) * sc;
            v1.z = (acc[i][6] + bias[o0 + 6]) * sc;
            v1.w = (acc[i][7] + bias[o0 + 7]) * sc;
            *(float4*)(dst + off)     = v0;
            *(float4*)(dst + off + 4) = v1;
        } else if (EPI == 1) {
            int win = m / NN, n = m - win * NN;
            int b = win >> 6, w = win & 63;
            int wr = w >> 3, wc = w & 7;
            int ir = n / 7, ic = n - ir * 7;
            int hf = wr * WS + ir + SS; if (hf >= HH)  hf -= HH;  // final = (shifted+3)%56
            int wf = wc * WS + ic + SS; if (wf >= WWD) wf -= WWD;
            size_t tok = (size_t)b * (HH * WWD) + hf * WWD + wf;
            size_t off = tok * CC + o0;
            float4 r0 = *(const float4*)(aux + off);
            float4 r1 = *(const float4*)(aux + off + 4);
            float4 v0, v1;
            v0.x = r0.x + acc[i][0] + bias[o0 + 0];
            v0.y = r0.y + acc[i][1] + bias[o0 + 1];
            v0.z = r0.z + acc[i][2] + bias[o0 + 2];
            v0.w = r0.w + acc[i][3] + bias[o0 + 3];
            v1.x = r1.x + acc[i][4] + bias[o0 + 4];
            v1.y = r1.y + acc[i][5] + bias[o0 + 5];
            v1.z = r1.z + acc[i][6] + bias[o0 + 6];
            v1.w = r1.w + acc[i][7] + bias[o0 + 7];
            *(float4*)(out0 + off)     = v0;
            *(float4*)(out0 + off + 4) = v1;
        } else if (EPI == 2) {
            size_t off = (size_t)m * Nn + o0;
            float4 v0, v1;
            float t;
            t = acc[i][0] + bias[o0 + 0]; v0.x = 0.5f * t * (1.f + erff(t * 0.70710678f));
            t = acc[i][1] + bias[o0 + 1]; v0.y = 0.5f * t * (1.f + erff(t * 0.70710678f));
            t = acc[i][2] + bias[o0 + 2]; v0.z = 0.5f * t * (1.f + erff(t * 0.70710678f));
            t = acc[i][3] + bias[o0 + 3]; v0.w = 0.5f * t * (1.f + erff(t * 0.70710678f));
            t = acc[i][4] + bias[o0 + 4]; v1.x = 0.5f * t * (1.f + erff(t * 0.70710678f));
            t = acc[i][5] + bias[o0 + 5]; v1.y = 0.5f * t * (1.f + erff(t * 0.70710678f));
            t = acc[i][6] + bias[o0 + 6]; v1.z = 0.5f * t * (1.f + erff(t * 0.70710678f));
            t = acc[i][7] + bias[o0 + 7]; v1.w = 0.5f * t * (1.f + erff(t * 0.70710678f));
            *(float4*)(out0 + off)     = v0;
            *(float4*)(out0 + off + 4) = v1;
        } else {
            size_t off = (size_t)m * CC + o0;
            float4 r0 = *(const float4*)(aux + off);
            float4 r1 = *(const float4*)(aux + off + 4);
            float4 v0, v1;
            v0.x = r0.x + acc[i][0] + bias[o0 + 0];
            v0.y = r0.y + acc[i][1] + bias[o0 + 1];
            v0.z = r0.z + acc[i][2] + bias[o0 + 2];
            v0.w = r0.w + acc[i][3] + bias[o0 + 3];
            v1.x = r1.x + acc[i][4] + bias[o0 + 4];
            v1.y = r1.y + acc[i][5] + bias[o0 + 5];
            v1.z = r1.z + acc[i][6] + bias[o0 + 6];
            v1.w = r1.w + acc[i][7] + bias[o0 + 7];
            *(float4*)(out0 + off)     = v0;
            *(float4*)(out0 + off + 4) = v1;
        }
    }
}

// ---------------------------------------------------------------------------
// Attention: one block per (window, head). 64 threads, threads 0..48 each own
// one query row. Rel-pos bias column staged in smem; shifted-window mask
// region ids computed arithmetically. Output written in [B_, N, C] layout.
// ---------------------------------------------------------------------------
__global__ void __launch_bounds__(64)
attn_kernel(const float* __restrict__ q, const float* __restrict__ k,
            const float* __restrict__ v, const float* __restrict__ rpb,
            float* __restrict__ out)
{
    int bx = blockIdx.x;
    int head = bx & 7;
    int win  = bx >> 3;
    int w  = win & 63;
    int wr = w >> 3, wc = w & 7;

    __shared__ float sk[NN * HD];
    __shared__ float sv[NN * HD];
    __shared__ float sb[169];
    __shared__ int   sreg[NN];

    int tid = threadIdx.x;
    size_t base = (size_t)((win * NHEAD + head) * NN) * HD;
    const float4* kin = (const float4*)(k + base);
    const float4* vin = (const float4*)(v + base);
    for (int i = tid; i < NN * HD / 4; i += 64) {
        ((float4*)sk)[i] = kin[i];
        ((float4*)sv)[i] = vin[i];
    }
    for (int i = tid; i < 169; i += 64) sb[i] = rpb[i * NHEAD + head];
    if (tid < NN) {
        int jr = tid / 7, jc = tid - jr * 7;
        int h0 = wr * WS + jr, w0 = wc * WS + jc;
        int rh = (h0 < HH - WS) ? 0 : ((h0 < HH - SS) ? 1 : 2);
        int rw = (w0 < WWD - WS) ? 0 : ((w0 < WWD - SS) ? 1 : 2);
        sreg[tid] = rh * 3 + rw;
    }
    __syncthreads();
    if (tid >= NN) return;

    const int i = tid;
    const int ir = i / 7, ic = i - ir * 7;
    const int regi = sreg[i];

    float qr[HD];
    const float* qp = q + base + (size_t)i * HD;
#pragma unroll
    for (int d = 0; d < HD; d += 4) {
        float4 t = *(const float4*)(qp + d);
        qr[d] = t.x; qr[d + 1] = t.y; qr[d + 2] = t.z; qr[d + 3] = t.w;
    }

    float s[NN];
    float mx = -1e30f;
#pragma unroll
    for (int j = 0; j < NN; j++) {
        float dot = 0.f;
#pragma unroll
        for (int d = 0; d < HD; d++) dot = fmaf(qr[d], sk[j * HD + d], dot);
        int jr = j / 7, jc = j - jr * 7;
        dot += sb[(ir - jr + 6) * 13 + (ic - jc + 6)];
        if (regi != sreg[j]) dot -= 100.f;
        s[j] = dot;
        mx = fmaxf(mx, dot);
    }
    float sum = 0.f;
#pragma unroll
    for (int j = 0; j < NN; j++) { float e = expf(s[j] - mx); s[j] = e; sum += e; }
    float inv = 1.f / sum;

    float acc[HD];
#pragma unroll
    for (int d = 0; d < HD; d++) acc[d] = 0.f;
#pragma unroll
    for (int j = 0; j < NN; j++) {
        float p = s[j] * inv;
#pragma unroll
        for (int d = 0; d < HD; d++) acc[d] = fmaf(p, sv[j * HD + d], acc[d]);
    }
    float* op = out + (size_t)(win * NN + i) * CC + head * HD;
#pragma unroll
    for (int d = 0; d < HD; d += 4) {
        float4 t = make_float4(acc[d], acc[d + 1], acc[d + 2], acc[d + 3]);
        *(float4*)(op + d) = t;
    }
}

// ---------------------------------------------------------------------------
extern "C" void kernel_launch(void* const* d_in, const int* in_sizes, int n_in,
                              void* d_out, int out_size)
{
    const float* x      = (const float*)d_in[0];
    const float* n1w    = (const float*)d_in[1];
    const float* n1b    = (const float*)d_in[2];
    const float* qkv_w  = (const float*)d_in[3];
    const float* qkv_b  = (const float*)d_in[4];
    const float* rpb    = (const float*)d_in[5];
    const float* proj_w = (const float*)d_in[6];
    const float* proj_b = (const float*)d_in[7];
    const float* n2w    = (const float*)d_in[8];
    const float* n2b    = (const float*)d_in[9];
    const float* fc1_w  = (const float*)d_in[10];
    const float* fc1_b  = (const float*)d_in[11];
    const float* fc2_w  = (const float*)d_in[12];
    const float* fc2_b  = (const float*)d_in[13];
    float* out = (float*)d_out;

    void* pA = nullptr; cudaGetSymbolAddress(&pA, g_bufA);
    void* pB = nullptr; cudaGetSymbolAddress(&pB, g_bufB);
    float* A  = (float*)pA;
    float* Bb = (float*)pB;
    const size_t QS = (size_t)MTOK * CC;

    float* qb   = A;            // quarter 0
    float* kb   = A + QS;       // quarter 1
    float* vb   = A + 2 * QS;   // quarter 2
    float* mlp  = A;            // whole A reused after attention
    float* hw   = Bb;           // half 0: LN1+shift+window output
    float* attn = Bb + QS;      // half 1: attention output
    float* x1   = Bb;           // half 0 reused: residual stream
    float* h2   = Bb + QS;      // half 1 reused: LN2 output

    // 1. LN1 + cyclic shift + window partition
    ln_kernel<<<MTOK, 256>>>(x, n1w, n1b, hw, 1);
    // 2. QKV GEMM -> q/k/v (per-head layout, q pre-scaled)
    {
        dim3 g(768 / 128, MTOK / 128);
        gemm_kernel<0><<<g, 256>>>(hw, qkv_w, qkv_b, nullptr, qb, kb, vb, CC, 768);
    }
    // 3. Windowed attention (+rel-pos bias, +shift mask, softmax)
    attn_kernel<<<BWIN * NHEAD, 64>>>(qb, kb, vb, rpb, attn);
    // 4. Proj GEMM + window reverse + unshift + residual
    {
        dim3 g(256 / 128, MTOK / 128);
        gemm_kernel<1><<<g, 256>>>(attn, proj_w, proj_b, x, x1, nullptr, nullptr, CC, 256);
    }
    // 5. LN2
    ln_kernel<<<MTOK, 256>>>(x1, n2w, n2b, h2, 0);
    // 6. FC1 + exact GELU
    {
        dim3 g(1024 / 128, MTOK / 128);
        gemm_kernel<2><<<g, 256>>>(h2, fc1_w, fc1_b, nullptr, mlp, nullptr, nullptr, CC, 1024);
    }
    // 7. FC2 + residual -> out
    {
        dim3 g(256 / 128, MTOK / 128);
        gemm_kernel<3><<<g, 256>>>(mlp, fc2_w, fc2_b, x1, out, nullptr, nullptr, HID, 256);
    }
}

// round 14
// speedup vs baseline: 1.8791x; 1.8791x over previous
#include <cuda_runtime.h>
#include <math.h>
#include <stdint.h>

#define BB    64
#define HH    56
#define WWD   56
#define CC    256
#define NHEAD 8
#define WS    7
#define SS    3
#define NN    49
#define HID   1024
#define NWIN  64
#define BWIN  (BB*NWIN)
#define MTOK  (BB*HH*WWD)
#define HD    32

// Scratch (static device globals; no allocations allowed).
__device__ float g_bufA[205520896];   // MTOK*HID
__device__ float g_bufB[102760448];   // MTOK*2*CC

// ---------------------------------------------------------------------------
// LayerNorm (+optional shift/window-partition) — unchanged from R3 (passed).
// ---------------------------------------------------------------------------
__global__ void __launch_bounds__(256)
ln_kernel(const float* __restrict__ x, const float* __restrict__ wt,
          const float* __restrict__ bs, float* __restrict__ out, int windowed)
{
    int m = blockIdx.x;
    int c = threadIdx.x;
    size_t src;
    if (windowed) {
        int win = m / NN, n = m - win * NN;
        int b = win >> 6, w = win & 63;
        int wr = w >> 3, wc = w & 7;
        int ir = n / 7, ic = n - ir * 7;
        int hs = wr * WS + ir + SS; if (hs >= HH)  hs -= HH;
        int wsd = wc * WS + ic + SS; if (wsd >= WWD) wsd -= WWD;
        src = (size_t)b * (HH * WWD) + hs * WWD + wsd;
    } else {
        src = (size_t)m;
    }
    float v = x[src * CC + c];
    float s = v, sq = v * v;
#pragma unroll
    for (int off = 16; off; off >>= 1) {
        s  += __shfl_xor_sync(0xffffffffu, s,  off);
        sq += __shfl_xor_sync(0xffffffffu, sq, off);
    }
    __shared__ float ss[8], ssq[8];
    int wid = c >> 5, lid = c & 31;
    if (lid == 0) { ss[wid] = s; ssq[wid] = sq; }
    __syncthreads();
    float ts = 0.f, tsq = 0.f;
#pragma unroll
    for (int i = 0; i < 8; i++) { ts += ss[i]; tsq += ssq[i]; }
    float mean = ts * (1.f / CC);
    float var  = tsq * (1.f / CC) - mean * mean;
    float r = rsqrtf(var + 1e-5f);
    out[(size_t)m * CC + c] = (v - mean) * r * wt[c] + bs[c];
}

// ---------------------------------------------------------------------------
// tf32 tensor-core GEMM: C[M,N] = A[M,K] @ W[N,K]^T
// CTA tile 128x256, BK=16, 8 warps (2x4), warp tile 64x64, m16n8k8 tf32 mma.
// Smem XOR swizzle m' = m ^ ((k&3)*8) ^ ((k>>3)*16): conflict-free frag reads
// AND conflict-free STS scatter. Double-buffered, register prefetch.
// Epilogues (C-fragment layout: thread owns rows lp/lp+8, cols lq*2,lq*2+1):
//  EPI 0: qkv -> scatter q/k/v [win,head,n,hd], q * hd^-0.5
//  EPI 1: proj -> window reverse + unshift + residual(aux=x)
//  EPI 2: fc1 -> exact GELU (row stride HID)
//  EPI 3: fc2 -> residual(aux=x1) (row stride CC)
// ---------------------------------------------------------------------------
__device__ __forceinline__ uint32_t f2tf(float f) {
    uint32_t u; asm("cvt.rna.tf32.f32 %0, %1;" : "=r"(u) : "f"(f)); return u;
}

#define MMA8(d, a, b) \
    asm("mma.sync.aligned.m16n8k8.row.col.f32.tf32.tf32.f32 " \
        "{%0,%1,%2,%3}, {%4,%5,%6,%7}, {%8,%9}, {%0,%1,%2,%3};" \
        : "+f"(d[0]), "+f"(d[1]), "+f"(d[2]), "+f"(d[3]) \
        : "r"(a[0]), "r"(a[1]), "r"(a[2]), "r"(a[3]), "r"(b[0]), "r"(b[1]))

template<int EPI>
__global__ void __launch_bounds__(256, 1)
gemm_tc(const float* __restrict__ A, const float* __restrict__ W,
        const float* __restrict__ bias, const float* __restrict__ aux,
        float* __restrict__ out0, float* __restrict__ out1,
        float* __restrict__ out2, int K)
{
    __shared__ uint32_t As[2][16 * 128];   // 16KB
    __shared__ uint32_t Bs[2][16 * 256];   // 32KB
    const int bm = blockIdx.y * 128;
    const int bn = blockIdx.x * 256;
    const int tid  = threadIdx.x;
    const int lane = tid & 31, warp = tid >> 5;
    const int wm = warp & 1, wn = warp >> 1;       // 2 x 4 warp grid
    const int lp = lane >> 2, lq = lane & 3;

    // loader mapping: thread covers 64B of one A row and of two W rows
    const int ra = tid >> 1;      // 0..127
    const int ha = tid & 1;       // k-half
    const float* gA  = A + (size_t)(bm + ra) * K + ha * 8;
    const float* gB0 = W + (size_t)(bn + ra) * K + ha * 8;
    const float* gB1 = W + (size_t)(bn + 128 + ra) * K + ha * 8;

    float acc[4][8][4];
#pragma unroll
    for (int t = 0; t < 4; t++)
#pragma unroll
        for (int u = 0; u < 8; u++)
#pragma unroll
            for (int c = 0; c < 4; c++) acc[t][u][c] = 0.f;

    float4 pa0, pa1, pb00, pb01, pb10, pb11;
    pa0  = *(const float4*)(gA);
    pa1  = *(const float4*)(gA + 4);
    pb00 = *(const float4*)(gB0);
    pb01 = *(const float4*)(gB0 + 4);
    pb10 = *(const float4*)(gB1);
    pb11 = *(const float4*)(gB1 + 4);

    auto sts_stage = [&](int st) {
        const float* a0p = (const float*)&pa0;  const float* a1p = (const float*)&pa1;
        const float* b0p = (const float*)&pb00; const float* b1p = (const float*)&pb01;
        const float* b2p = (const float*)&pb10; const float* b3p = (const float*)&pb11;
#pragma unroll
        for (int j = 0; j < 4; j++) {
            const int k0 = ha * 8 + j;
            const int k1 = k0 + 4;
            const int sw = (j * 8) ^ (ha * 16);      // (k&3)*8 ^ (k>>3)*16, same for k0,k1
            As[st][k0 * 128 + (ra ^ sw)]         = f2tf(a0p[j]);
            As[st][k1 * 128 + (ra ^ sw)]         = f2tf(a1p[j]);
            Bs[st][k0 * 256 + (ra ^ sw)]         = f2tf(b0p[j]);
            Bs[st][k1 * 256 + (ra ^ sw)]         = f2tf(b1p[j]);
            Bs[st][k0 * 256 + ((ra + 128) ^ sw)] = f2tf(b2p[j]);
            Bs[st][k1 * 256 + ((ra + 128) ^ sw)] = f2tf(b3p[j]);
        }
    };

    auto compute = [&](int st) {
#pragma unroll
        for (int s = 0; s < 2; s++) {
            const int swz = (lq * 8) ^ (s * 16);
            const uint32_t* ak = &As[st][(s * 8 + lq) * 128];
            const uint32_t* bk = &Bs[st][(s * 8 + lq) * 256];
            uint32_t af[4][4];
#pragma unroll
            for (int t = 0; t < 4; t++) {
                const int mi = (wm * 64 + t * 16 + lp) ^ swz;
                af[t][0] = ak[mi];
                af[t][1] = ak[mi ^ 8];
                af[t][2] = ak[mi + 512];
                af[t][3] = ak[(mi ^ 8) + 512];
            }
            uint32_t bf[8][2];
#pragma unroll
            for (int u = 0; u < 8; u++) {
                const int ni = (wn * 64 + u * 8 + lp) ^ swz;
                bf[u][0] = bk[ni];
                bf[u][1] = bk[ni + 1024];
            }
#pragma unroll
            for (int t = 0; t < 4; t++)
#pragma unroll
                for (int u = 0; u < 8; u++)
                    MMA8(acc[t][u], af[t], bf[u]);
        }
    };

    sts_stage(0);
    __syncthreads();
    const int nit = K >> 4;
    for (int it = 0; it < nit; ++it) {
        const int cur = it & 1;
        if (it + 1 < nit) {
            const float* pA  = gA  + (it + 1) * 16;
            const float* pB0 = gB0 + (it + 1) * 16;
            const float* pB1 = gB1 + (it + 1) * 16;
            pa0  = *(const float4*)(pA);
            pa1  = *(const float4*)(pA + 4);
            pb00 = *(const float4*)(pB0);
            pb01 = *(const float4*)(pB0 + 4);
            pb10 = *(const float4*)(pB1);
            pb11 = *(const float4*)(pB1 + 4);
        }
        compute(cur);
        if (it + 1 < nit) sts_stage(cur ^ 1);
        __syncthreads();
    }

    // ---------------- epilogue ----------------
    const int n_base = bn + wn * 64;
#pragma unroll
    for (int t = 0; t < 4; t++) {
        const int rbase = bm + wm * 64 + t * 16 + lp;
#pragma unroll
        for (int half = 0; half < 2; half++) {
            const int r = rbase + half * 8;
            if (EPI == 0) {
                const int win = r / NN, n = r - win * NN;
                const int wbase = win * (NHEAD * NN) + n;
#pragma unroll
                for (int u = 0; u < 8; u++) {
                    const int col = n_base + u * 8 + lq * 2;
                    const int si = col >> 8;
                    const int h  = (col >> 5) & 7;
                    const int d0 = col & 31;
                    const float sc = (si == 0) ? 0.17677669529663687f : 1.0f;
                    float* dst = (si == 0) ? out0 : (si == 1) ? out1 : out2;
                    const size_t off = (size_t)(wbase + h * NN) * HD + d0;
                    const float2 bb = *(const float2*)(bias + col);
                    float2 v;
                    v.x = (acc[t][u][half * 2 + 0] + bb.x) * sc;
                    v.y = (acc[t][u][half * 2 + 1] + bb.y) * sc;
                    *(float2*)(dst + off) = v;
                }
            } else if (EPI == 1) {
                const int win = r / NN, n = r - win * NN;
                const int b = win >> 6, w = win & 63;
                const int wr = w >> 3, wc = w & 7;
                const int ir = n / 7, ic = n - ir * 7;
                int hf = wr * WS + ir + SS; if (hf >= HH)  hf -= HH;
                int wf = wc * WS + ic + SS; if (wf >= WWD) wf -= WWD;
                const size_t tok = (size_t)b * (HH * WWD) + hf * WWD + wf;
#pragma unroll
                for (int u = 0; u < 8; u++) {
                    const int col = n_base + u * 8 + lq * 2;
                    const size_t off = tok * CC + col;
                    const float2 rr = *(const float2*)(aux + off);
                    const float2 bb = *(const float2*)(bias + col);
                    float2 v;
                    v.x = rr.x + acc[t][u][half * 2 + 0] + bb.x;
                    v.y = rr.y + acc[t][u][half * 2 + 1] + bb.y;
                    *(float2*)(out0 + off) = v;
                }
            } else if (EPI == 2) {
#pragma unroll
                for (int u = 0; u < 8; u++) {
                    const int col = n_base + u * 8 + lq * 2;
                    const size_t off = (size_t)r * HID + col;
                    const float2 bb = *(const float2*)(bias + col);
                    float t0 = acc[t][u][half * 2 + 0] + bb.x;
                    float t1 = acc[t][u][half * 2 + 1] + bb.y;
                    float2 v;
                    v.x = 0.5f * t0 * (1.f + erff(t0 * 0.70710678118654752f));
                    v.y = 0.5f * t1 * (1.f + erff(t1 * 0.70710678118654752f));
                    *(float2*)(out0 + off) = v;
                }
            } else {
#pragma unroll
                for (int u = 0; u < 8; u++) {
                    const int col = n_base + u * 8 + lq * 2;
                    const size_t off = (size_t)r * CC + col;
                    const float2 rr = *(const float2*)(aux + off);
                    const float2 bb = *(const float2*)(bias + col);
                    float2 v;
                    v.x = rr.x + acc[t][u][half * 2 + 0] + bb.x;
                    v.y = rr.y + acc[t][u][half * 2 + 1] + bb.y;
                    *(float2*)(out0 + off) = v;
                }
            }
        }
    }
}

// ---------------------------------------------------------------------------
// Attention — unchanged from R3 (passed).
// ---------------------------------------------------------------------------
__global__ void __launch_bounds__(64)
attn_kernel(const float* __restrict__ q, const float* __restrict__ k,
            const float* __restrict__ v, const float* __restrict__ rpb,
            float* __restrict__ out)
{
    int bx = blockIdx.x;
    int head = bx & 7;
    int win  = bx >> 3;
    int w  = win & 63;
    int wr = w >> 3, wc = w & 7;

    __shared__ float sk[NN * HD];
    __shared__ float sv[NN * HD];
    __shared__ float sb[169];
    __shared__ int   sreg[NN];

    int tid = threadIdx.x;
    size_t base = (size_t)((win * NHEAD + head) * NN) * HD;
    const float4* kin = (const float4*)(k + base);
    const float4* vin = (const float4*)(v + base);
    for (int i = tid; i < NN * HD / 4; i += 64) {
        ((float4*)sk)[i] = kin[i];
        ((float4*)sv)[i] = vin[i];
    }
    for (int i = tid; i < 169; i += 64) sb[i] = rpb[i * NHEAD + head];
    if (tid < NN) {
        int jr = tid / 7, jc = tid - jr * 7;
        int h0 = wr * WS + jr, w0 = wc * WS + jc;
        int rh = (h0 < HH - WS) ? 0 : ((h0 < HH - SS) ? 1 : 2);
        int rw = (w0 < WWD - WS) ? 0 : ((w0 < WWD - SS) ? 1 : 2);
        sreg[tid] = rh * 3 + rw;
    }
    __syncthreads();
    if (tid >= NN) return;

    const int i = tid;
    const int ir = i / 7, ic = i - ir * 7;
    const int regi = sreg[i];

    float qr[HD];
    const float* qp = q + base + (size_t)i * HD;
#pragma unroll
    for (int d = 0; d < HD; d += 4) {
        float4 t = *(const float4*)(qp + d);
        qr[d] = t.x; qr[d + 1] = t.y; qr[d + 2] = t.z; qr[d + 3] = t.w;
    }

    float s[NN];
    float mx = -1e30f;
#pragma unroll
    for (int j = 0; j < NN; j++) {
        float dot = 0.f;
#pragma unroll
        for (int d = 0; d < HD; d++) dot = fmaf(qr[d], sk[j * HD + d], dot);
        int jr = j / 7, jc = j - jr * 7;
        dot += sb[(ir - jr + 6) * 13 + (ic - jc + 6)];
        if (regi != sreg[j]) dot -= 100.f;
        s[j] = dot;
        mx = fmaxf(mx, dot);
    }
    float sum = 0.f;
#pragma unroll
    for (int j = 0; j < NN; j++) { float e = expf(s[j] - mx); s[j] = e; sum += e; }
    float inv = 1.f / sum;

    float acc[HD];
#pragma unroll
    for (int d = 0; d < HD; d++) acc[d] = 0.f;
#pragma unroll
    for (int j = 0; j < NN; j++) {
        float p = s[j] * inv;
#pragma unroll
        for (int d = 0; d < HD; d++) acc[d] = fmaf(p, sv[j * HD + d], acc[d]);
    }
    float* op = out + (size_t)(win * NN + i) * CC + head * HD;
#pragma unroll
    for (int d = 0; d < HD; d += 4) {
        float4 t = make_float4(acc[d], acc[d + 1], acc[d + 2], acc[d + 3]);
        *(float4*)(op + d) = t;
    }
}

// ---------------------------------------------------------------------------
extern "C" void kernel_launch(void* const* d_in, const int* in_sizes, int n_in,
                              void* d_out, int out_size)
{
    const float* x      = (const float*)d_in[0];
    const float* n1w    = (const float*)d_in[1];
    const float* n1b    = (const float*)d_in[2];
    const float* qkv_w  = (const float*)d_in[3];
    const float* qkv_b  = (const float*)d_in[4];
    const float* rpb    = (const float*)d_in[5];
    const float* proj_w = (const float*)d_in[6];
    const float* proj_b = (const float*)d_in[7];
    const float* n2w    = (const float*)d_in[8];
    const float* n2b    = (const float*)d_in[9];
    const float* fc1_w  = (const float*)d_in[10];
    const float* fc1_b  = (const float*)d_in[11];
    const float* fc2_w  = (const float*)d_in[12];
    const float* fc2_b  = (const float*)d_in[13];
    float* out = (float*)d_out;

    void* pA = nullptr; cudaGetSymbolAddress(&pA, g_bufA);
    void* pB = nullptr; cudaGetSymbolAddress(&pB, g_bufB);
    float* A  = (float*)pA;
    float* Bb = (float*)pB;
    const size_t QS = (size_t)MTOK * CC;

    float* qb   = A;            // quarter 0
    float* kb   = A + QS;       // quarter 1
    float* vb   = A + 2 * QS;   // quarter 2
    float* mlp  = A;            // whole A reused after attention
    float* hw   = Bb;           // half 0: LN1+shift+window output
    float* attn = Bb + QS;      // half 1: attention output
    float* x1   = Bb;           // half 0 reused: residual stream
    float* h2   = Bb + QS;      // half 1 reused: LN2 output

    // 1. LN1 + cyclic shift + window partition
    ln_kernel<<<MTOK, 256>>>(x, n1w, n1b, hw, 1);
    // 2. QKV GEMM (tf32 TC) -> q/k/v
    {
        dim3 g(768 / 256, MTOK / 128);
        gemm_tc<0><<<g, 256>>>(hw, qkv_w, qkv_b, nullptr, qb, kb, vb, CC);
    }
    // 3. Windowed attention
    attn_kernel<<<BWIN * NHEAD, 64>>>(qb, kb, vb, rpb, attn);
    // 4. Proj GEMM + window reverse + unshift + residual
    {
        dim3 g(256 / 256, MTOK / 128);
        gemm_tc<1><<<g, 256>>>(attn, proj_w, proj_b, x, x1, nullptr, nullptr, CC);
    }
    // 5. LN2
    ln_kernel<<<MTOK, 256>>>(x1, n2w, n2b, h2, 0);
    // 6. FC1 + exact GELU
    {
        dim3 g(HID / 256, MTOK / 128);
        gemm_tc<2><<<g, 256>>>(h2, fc1_w, fc1_b, nullptr, mlp, nullptr, nullptr, CC);
    }
    // 7. FC2 + residual -> out
    {
        dim3 g(256 / 256, MTOK / 128);
        gemm_tc<3><<<g, 256>>>(mlp, fc2_w, fc2_b, x1, out, nullptr, nullptr, HID);
    }
}